// round 15
// baseline (speedup 1.0000x reference)
#include <cuda_runtime.h>
#include <cuda_fp16.h>
#include <cstdint>
#include <cstddef>

// Problem dims
#define BROWS 4096
#define NB1   128
#define I1    64
#define MMID  64
#define O2    128
#define BCH   2048   // batch chunk (t chunk = 32 MB fp16, L2-resident)
#define NCHK  2

__device__ __half g_xh[(size_t)BROWS * 8192];        // 64 MB: fp16(x)
__device__ __half g_th[(size_t)BCH * MMID * NB1];    // 32 MB: t chunk [b][m][n]
__device__ __half g_w1h[NB1 * MMID * I1];            // [n][m][i] softmaxed fp16
__device__ __half g_w2h[MMID * O2 * NB1];            // [m][o][n] softmaxed fp16

__device__ __forceinline__ unsigned pack2(float x, float y) {
    __half2 h = __floats2half2_rn(x, y);
    return *(unsigned*)&h;
}

__device__ __forceinline__ void mma_f16(float& d0, float& d1, float& d2, float& d3,
                                        unsigned a0, unsigned a1, unsigned a2, unsigned a3,
                                        unsigned b0, unsigned b1) {
    asm volatile(
        "mma.sync.aligned.m16n8k16.row.col.f32.f16.f16.f32 "
        "{%0,%1,%2,%3}, {%4,%5,%6,%7}, {%8,%9}, {%0,%1,%2,%3};"
        : "+f"(d0), "+f"(d1), "+f"(d2), "+f"(d3)
        : "r"(a0), "r"(a1), "r"(a2), "r"(a3), "r"(b0), "r"(b1));
}

__device__ __forceinline__ void ldsm4(unsigned& r0, unsigned& r1, unsigned& r2, unsigned& r3,
                                      const void* p) {
    unsigned a = (unsigned)__cvta_generic_to_shared(p);
    asm volatile("ldmatrix.sync.aligned.m8n8.x4.shared.b16 {%0,%1,%2,%3}, [%4];"
                 : "=r"(r0), "=r"(r1), "=r"(r2), "=r"(r3) : "r"(a));
}

__device__ __forceinline__ void cp16(void* dst_smem, const void* src) {
    unsigned d = (unsigned)__cvta_generic_to_shared(dst_smem);
    asm volatile("cp.async.cg.shared.global [%0], [%1], 16;" :: "r"(d), "l"(src));
}
__device__ __forceinline__ void cp_commit() { asm volatile("cp.async.commit_group;"); }
template<int N> __device__ __forceinline__ void cp_wait() {
    asm volatile("cp.async.wait_group %0;" :: "n"(N));
}

// ---------------- x -> fp16 streaming convert ----------------
__global__ __launch_bounds__(256) void convert_x_kernel(const float* __restrict__ x) {
    size_t base = (size_t)blockIdx.x * 4096 + threadIdx.x;
    const float4* src = (const float4*)x;
    uint2* dst = (uint2*)g_xh;
#pragma unroll
    for (int t = 0; t < 16; t++) {
        float4 v = src[base + (size_t)t * 256];
        dst[base + (size_t)t * 256] = make_uint2(pack2(v.x, v.y), pack2(v.z, v.w));
    }
}

// ---------------- fused softmax precompute ----------------
__global__ void softmax_fused_kernel(const float* __restrict__ c1,
                                     const float* __restrict__ c2) {
    extern __shared__ float sm[];
    int tid = threadIdx.x;              // 128
    if (blockIdx.x < NB1) {
        int n = blockIdx.x;
        float* s  = sm;                 // [i][m] 64x64
        float* so = sm + I1 * MMID;     // [m][i] pitch 68
        const float4* src = (const float4*)(c1 + (size_t)n * I1 * MMID);
#pragma unroll
        for (int i = 0; i < 8; i++) ((float4*)s)[tid + i * 128] = src[tid + i * 128];
        __syncthreads();
        if (tid < MMID) {
            int m = tid;
            float v[I1];
            float mx = -1e30f;
#pragma unroll
            for (int i = 0; i < I1; i++) { v[i] = s[i * MMID + m] * 3.0f; mx = fmaxf(mx, v[i]); }
            float sum = 0.0f;
#pragma unroll
            for (int i = 0; i < I1; i++) { v[i] = expf(v[i] - mx); sum += v[i]; }
            float inv = 1.0f / sum;
#pragma unroll
            for (int i = 0; i < I1; i++) so[m * 68 + i] = v[i] * inv;
        }
        __syncthreads();
        __half* dst = g_w1h + (size_t)n * MMID * I1;
#pragma unroll
        for (int t = 0; t < 8; t++) {
            int idx = tid + t * 128;    // 1024 float4 units
            int r = idx >> 4, c = idx & 15;
            float4 q = *(float4*)(so + r * 68 + c * 4);
            uint2 h = make_uint2(pack2(q.x, q.y), pack2(q.z, q.w));
            *(uint2*)(dst + r * 64 + c * 4) = h;
        }
    } else {
        int m = blockIdx.x - NB1;
        float* sin  = sm;                   // [n][o] 128x128
        float* sout = sm + NB1 * O2;        // [o][n] pitch 132
        const float4* src = (const float4*)(c2 + (size_t)m * NB1 * O2);
#pragma unroll
        for (int i = 0; i < 32; i++) ((float4*)sin)[tid + i * 128] = src[tid + i * 128];
        __syncthreads();
        int o = tid;
        float mx = -1e30f;
        for (int n = 0; n < NB1; n++) mx = fmaxf(mx, sin[n * O2 + o] * 3.0f);
        float sum = 0.0f;
        for (int n = 0; n < NB1; n++) {
            float e = expf(sin[n * O2 + o] * 3.0f - mx);
            sout[o * 132 + n] = e;
            sum += e;
        }
        float inv = 1.0f / sum;
        __syncthreads();
        sin[o] = inv;                       // per-o scale
        __syncthreads();
        __half* dst = g_w2h + (size_t)m * O2 * NB1;
#pragma unroll
        for (int t = 0; t < 32; t++) {
            int idx = tid + t * 128;        // 4096 float4 units
            int r = idx >> 5, c = idx & 31;
            float iv = sin[r];
            float4 q = *(float4*)(sout + r * 132 + c * 4);
            uint2 h = make_uint2(pack2(q.x * iv, q.y * iv), pack2(q.z * iv, q.w * iv));
            *(uint2*)(dst + r * 128 + c * 4) = h;
        }
    }
}

// ---------------- stage 1 (fp16 mma, 512 thr, FULL prefetch) ----------------
// CTA: 64 b x 4 n, 512 thr (16 warps), 2 CTAs/SM. Warp grid 4(b:16) x 4(m:16).
// 4 buffers, ALL loads issued in prologue; loop = wait ladder + barrier + compute.
#define S1PITCH 144                     // bytes per row (72 halves)
#define S1ATILE (64 * S1PITCH)          // 9216 B
#define S1BUF   (2 * S1ATILE)           // A + B = 18432 B
__global__ __launch_bounds__(512, 2) void stage1_kernel(int chunk) {
    extern __shared__ char sm1[];
    int b0l = blockIdx.x * 64;
    int bg0 = chunk * BCH + b0l;
    int ng0 = blockIdx.y * 4;
    int tid = threadIdx.x;
    int wid = tid >> 5, lane = tid & 31, g = lane >> 2, tg = lane & 3;
    int wrow = (wid & 3) * 16;
    int wcol = (wid >> 2) * 16;

    auto issue = [&](int j) {
        int n = ng0 + j;
        char* Ab = sm1 + j * S1BUF;
        char* Bb = Ab + S1ATILE;
        int r = tid >> 3, c = tid & 7;          // 512 thr: 64 rows x 8 cols of 16B
        cp16(Ab + r * S1PITCH + c * 16, g_xh + (size_t)(bg0 + r) * 8192 + n * 64 + c * 8);
        cp16(Bb + r * S1PITCH + c * 16, g_w1h + ((size_t)n * 64 + r) * 64 + c * 8);
        cp_commit();
    };

    float acc[4][2][4];
#pragma unroll
    for (int a = 0; a < 4; a++)
#pragma unroll
        for (int b = 0; b < 2; b++)
#pragma unroll
            for (int c = 0; c < 4; c++) acc[a][b][c] = 0.0f;

    issue(0); issue(1); issue(2); issue(3);     // everything in flight

    int arow = wrow + (lane & 15);
    int acolh = (lane >> 4) * 8;                         // halves
    int brow_base = ((lane >> 4) << 3) + (lane & 7);
    int bcolh = ((lane >> 3) & 1) * 8;

#pragma unroll
    for (int j = 0; j < 4; j++) {
        if (j == 0) cp_wait<3>(); else if (j == 1) cp_wait<2>();
        else if (j == 2) cp_wait<1>(); else cp_wait<0>();
        __syncthreads();                         // visibility of other threads' cp.async
        char* Ab = sm1 + j * S1BUF;
        char* Bb = Ab + S1ATILE;
#pragma unroll
        for (int kk = 0; kk < 4; kk++) {
            int k0 = kk * 16;
            unsigned a0, a1, a2, a3;
            ldsm4(a0, a1, a2, a3, Ab + arow * S1PITCH + (k0 + acolh) * 2);
            unsigned b0g0, b1g0, b0g1, b1g1;
            ldsm4(b0g0, b1g0, b0g1, b1g1,
                  Bb + (wcol + brow_base) * S1PITCH + (k0 + bcolh) * 2);
            mma_f16(acc[j][0][0], acc[j][0][1], acc[j][0][2], acc[j][0][3],
                    a0, a1, a2, a3, b0g0, b1g0);
            mma_f16(acc[j][1][0], acc[j][1][1], acc[j][1][2], acc[j][1][3],
                    a0, a1, a2, a3, b0g1, b1g1);
        }
    }

    // flush: t[b_local][m][ng0..ng0+3] packed fp16 (8B stores over 4 n)
#pragma unroll
    for (int o = 0; o < 2; o++) {
#pragma unroll
        for (int rr = 0; rr < 2; rr++) {
#pragma unroll
            for (int c = 0; c < 2; c++) {
                int row = b0l + wrow + g + rr * 8;
                int col = wcol + o * 8 + tg * 2 + c;
                int s = rr * 2 + c;
                uint2 v = make_uint2(pack2(acc[0][o][s], acc[1][o][s]),
                                     pack2(acc[2][o][s], acc[3][o][s]));
                *(uint2*)(g_th + ((size_t)row * 64 + col) * 128 + ng0) = v;
            }
        }
    }
}

// ---------------- stage 2 (fp16 mma, 512 thr, FULL prefetch) ----------------
// CTA: 128 b x 64 o (grid.z = o-half), 512 thr (16 warps), 2 CTAs/SM.
// Warp grid 8(b:16) x 2(o:32). K=128 in 4 chunks of 32, 4 buffers, all prefetched.
#define S2PITCH 80                      // bytes per row (40 halves)
#define S2ATILE (128 * S2PITCH)         // 10240 B
#define S2BTILE (64 * S2PITCH)          // 5120 B
#define S2BUF   (S2ATILE + S2BTILE)     // 15360 B
__global__ __launch_bounds__(512, 2) void stage2_kernel(float* __restrict__ out, int chunk) {
    extern __shared__ char sm2[];
    int b0l = blockIdx.x * 128;
    int bg0 = chunk * BCH + b0l;
    int m  = blockIdx.y;
    int o0 = blockIdx.z * 64;
    int tid = threadIdx.x;
    int wid = tid >> 5, lane = tid & 31, g = lane >> 2, tg = lane & 3;
    int wrow = (wid & 7) * 16;
    int wcol = (wid >> 3) * 32;

    auto issue = [&](int kc) {
        int k0 = kc * 32;
        char* Ab = sm2 + kc * S2BUF;
        char* Bb = Ab + S2ATILE;
        {                                        // A: 512 units, 128 rows x 4
            int r = tid >> 2, c = tid & 3;
            cp16(Ab + r * S2PITCH + c * 16,
                 g_th + ((size_t)(b0l + r) * 64 + m) * 128 + k0 + c * 8);
        }
        if (tid < 256) {                         // B: 256 units, 64 rows x 4
            int r = tid >> 2, c = tid & 3;
            cp16(Bb + r * S2PITCH + c * 16,
                 g_w2h + ((size_t)m * 128 + o0 + r) * 128 + k0 + c * 8);
        }
        cp_commit();
    };

    float acc[4][4];
#pragma unroll
    for (int b = 0; b < 4; b++)
#pragma unroll
        for (int c = 0; c < 4; c++) acc[b][c] = 0.0f;

    issue(0); issue(1); issue(2); issue(3);

    int arow = wrow + (lane & 15);
    int acolh = (lane >> 4) * 8;
    int brow_base = ((lane >> 4) << 3) + (lane & 7);
    int bcolh = ((lane >> 3) & 1) * 8;

#pragma unroll
    for (int kc = 0; kc < 4; kc++) {
        if (kc == 0) cp_wait<3>(); else if (kc == 1) cp_wait<2>();
        else if (kc == 2) cp_wait<1>(); else cp_wait<0>();
        __syncthreads();
        char* Ab = sm2 + kc * S2BUF;
        char* Bb = Ab + S2ATILE;
#pragma unroll
        for (int kk = 0; kk < 2; kk++) {
            int k0 = kk * 16;
            unsigned a0, a1, a2, a3;
            ldsm4(a0, a1, a2, a3, Ab + arow * S2PITCH + (k0 + acolh) * 2);
#pragma unroll
            for (int p = 0; p < 2; p++) {
                unsigned b0g0, b1g0, b0g1, b1g1;
                ldsm4(b0g0, b1g0, b0g1, b1g1,
                      Bb + (wcol + p * 16 + brow_base) * S2PITCH + (k0 + bcolh) * 2);
                mma_f16(acc[2*p][0], acc[2*p][1], acc[2*p][2], acc[2*p][3],
                        a0, a1, a2, a3, b0g0, b1g0);
                mma_f16(acc[2*p+1][0], acc[2*p+1][1], acc[2*p+1][2], acc[2*p+1][3],
                        a0, a1, a2, a3, b0g1, b1g1);
            }
        }
    }

    // flush: out[b][m*128 + o]
#pragma unroll
    for (int nt = 0; nt < 4; nt++) {
        int col = o0 + wcol + nt * 8 + tg * 2;
        int r = bg0 + wrow + g;
        float* dst = out + (size_t)r * 8192 + m * 128 + col;
        *(float2*)dst = make_float2(acc[nt][0], acc[nt][1]);
        *(float2*)(dst + (size_t)8 * 8192) = make_float2(acc[nt][2], acc[nt][3]);
    }
}

// ---------------- launch ----------------
extern "C" void kernel_launch(void* const* d_in, const int* in_sizes, int n_in,
                              void* d_out, int out_size) {
    const float* x = nullptr;
    const float* c1 = nullptr;
    const float* c2 = nullptr;
    for (int i = 0; i < n_in; i++) {
        if (in_sizes[i] == BROWS * 8192)            x  = (const float*)d_in[i];
        else if (in_sizes[i] == NB1 * I1 * MMID)    c1 = (const float*)d_in[i];
        else if (in_sizes[i] == MMID * NB1 * O2)    c2 = (const float*)d_in[i];
    }

    const int smem_sm = (NB1 * O2 + O2 * 132) * sizeof(float);    // ~130 KB (c2 path)
    const int smem_s1 = 4 * S1BUF;                                // 73.7 KB
    const int smem_s2 = 4 * S2BUF;                                // 61.4 KB
    cudaFuncSetAttribute(softmax_fused_kernel, cudaFuncAttributeMaxDynamicSharedMemorySize, smem_sm);
    cudaFuncSetAttribute(stage1_kernel, cudaFuncAttributeMaxDynamicSharedMemorySize, smem_s1);
    cudaFuncSetAttribute(stage2_kernel, cudaFuncAttributeMaxDynamicSharedMemorySize, smem_s2);

    convert_x_kernel<<<2048, 256>>>(x);
    softmax_fused_kernel<<<NB1 + MMID, 128, smem_sm>>>(c1, c2);
    for (int c = 0; c < NCHK; c++) {
        stage1_kernel<<<dim3(BCH / 64, NB1 / 4), 512, smem_s1>>>(c);
        stage2_kernel<<<dim3(BCH / 128, MMID, 2), 512, smem_s2>>>((float*)d_out, c);
    }
}

// round 17
// speedup vs baseline: 1.6700x; 1.6700x over previous
#include <cuda_runtime.h>
#include <cuda_fp16.h>
#include <cstdint>
#include <cstddef>

// Problem dims
#define BROWS 4096
#define NB1   128
#define I1    64
#define MMID  64
#define O2    128
#define BCH   2048
#define NCHK  2
#define CHSZ  ((size_t)BCH * MMID * NB1)

// ping-pong t buffers: [buf][b_local][m][n] (n contiguous), fp16
__device__ __half g_th[2 * CHSZ];                    // 128 MB
__device__ __half g_w1h[NB1 * MMID * I1];            // [n][m][i] softmaxed fp16
__device__ __half g_w2h[MMID * O2 * NB1];            // [m][o][n] softmaxed fp16

__device__ __forceinline__ unsigned pack2(float x, float y) {
    __half2 h = __floats2half2_rn(x, y);
    return *(unsigned*)&h;
}

__device__ __forceinline__ void mma_f16(float& d0, float& d1, float& d2, float& d3,
                                        unsigned a0, unsigned a1, unsigned a2, unsigned a3,
                                        unsigned b0, unsigned b1) {
    asm volatile(
        "mma.sync.aligned.m16n8k16.row.col.f32.f16.f16.f32 "
        "{%0,%1,%2,%3}, {%4,%5,%6,%7}, {%8,%9}, {%0,%1,%2,%3};"
        : "+f"(d0), "+f"(d1), "+f"(d2), "+f"(d3)
        : "r"(a0), "r"(a1), "r"(a2), "r"(a3), "r"(b0), "r"(b1));
}

__device__ __forceinline__ void ldsm4(unsigned& r0, unsigned& r1, unsigned& r2, unsigned& r3,
                                      const void* p) {
    unsigned a = (unsigned)__cvta_generic_to_shared(p);
    asm volatile("ldmatrix.sync.aligned.m8n8.x4.shared.b16 {%0,%1,%2,%3}, [%4];"
                 : "=r"(r0), "=r"(r1), "=r"(r2), "=r"(r3) : "r"(a));
}

__device__ __forceinline__ void cp16(void* dst_smem, const void* src) {
    unsigned d = (unsigned)__cvta_generic_to_shared(dst_smem);
    asm volatile("cp.async.cg.shared.global [%0], [%1], 16;" :: "r"(d), "l"(src));
}
__device__ __forceinline__ void cp_commit() { asm volatile("cp.async.commit_group;"); }
template<int N> __device__ __forceinline__ void cp_wait() {
    asm volatile("cp.async.wait_group %0;" :: "n"(N));
}

// ---------------- fused softmax precompute ----------------
__global__ void softmax_fused_kernel(const float* __restrict__ c1,
                                     const float* __restrict__ c2) {
    extern __shared__ float sm[];
    int tid = threadIdx.x;              // 128
    if (blockIdx.x < NB1) {
        int n = blockIdx.x;
        float* s  = sm;                 // [i][m] 64x64
        float* so = sm + I1 * MMID;     // [m][i] pitch 68
        const float4* src = (const float4*)(c1 + (size_t)n * I1 * MMID);
#pragma unroll
        for (int i = 0; i < 8; i++) ((float4*)s)[tid + i * 128] = src[tid + i * 128];
        __syncthreads();
        if (tid < MMID) {
            int m = tid;
            float v[I1];
            float mx = -1e30f;
#pragma unroll
            for (int i = 0; i < I1; i++) { v[i] = s[i * MMID + m] * 3.0f; mx = fmaxf(mx, v[i]); }
            float sum = 0.0f;
#pragma unroll
            for (int i = 0; i < I1; i++) { v[i] = expf(v[i] - mx); sum += v[i]; }
            float inv = 1.0f / sum;
#pragma unroll
            for (int i = 0; i < I1; i++) so[m * 68 + i] = v[i] * inv;
        }
        __syncthreads();
        __half* dst = g_w1h + (size_t)n * MMID * I1;
#pragma unroll
        for (int t = 0; t < 8; t++) {
            int idx = tid + t * 128;    // 1024 float4 units
            int r = idx >> 4, c = idx & 15;
            float4 q = *(float4*)(so + r * 68 + c * 4);
            uint2 h = make_uint2(pack2(q.x, q.y), pack2(q.z, q.w));
            *(uint2*)(dst + r * 64 + c * 4) = h;
        }
    } else {
        int m = blockIdx.x - NB1;
        float* sin  = sm;                   // [n][o] 128x128
        float* sout = sm + NB1 * O2;        // [o][n] pitch 132
        const float4* src = (const float4*)(c2 + (size_t)m * NB1 * O2);
#pragma unroll
        for (int i = 0; i < 32; i++) ((float4*)sin)[tid + i * 128] = src[tid + i * 128];
        __syncthreads();
        int o = tid;
        float mx = -1e30f;
        for (int n = 0; n < NB1; n++) mx = fmaxf(mx, sin[n * O2 + o] * 3.0f);
        float sum = 0.0f;
        for (int n = 0; n < NB1; n++) {
            float e = expf(sin[n * O2 + o] * 3.0f - mx);
            sout[o * 132 + n] = e;
            sum += e;
        }
        float inv = 1.0f / sum;
        __syncthreads();
        sin[o] = inv;                       // per-o scale
        __syncthreads();
        __half* dst = g_w2h + (size_t)m * O2 * NB1;
#pragma unroll
        for (int t = 0; t < 32; t++) {
            int idx = tid + t * 128;        // 4096 float4 units
            int r = idx >> 5, c = idx & 31;
            float iv = sin[r];
            float4 q = *(float4*)(sout + r * 132 + c * 4);
            uint2 h = make_uint2(pack2(q.x * iv, q.y * iv), pack2(q.z * iv, q.w * iv));
            *(uint2*)(dst + r * 128 + c * 4) = h;
        }
    }
}

// ---------------- stage-1 body (round-12 proven): 64b x 4n, LDG fp32 -> STS fp16 ----
#define S1PITCH 144                     // bytes per row (72 halves)
#define S1TILE  (64 * S1PITCH)          // 9216 B
#define S1BUF   (2 * S1TILE)            // A + B per stage = 18432 B
__device__ __forceinline__ void s1_body(char* sm1, const float* __restrict__ x,
                                        int id, int chunk) {
    int b0l = (id & 31) * 64;
    int bg0 = chunk * BCH + b0l;
    int ng0 = (id >> 5) * 4;
    __half* th = g_th + (size_t)(chunk & 1) * CHSZ;
    int tid = threadIdx.x;
    int wid = tid >> 5, lane = tid & 31, g = lane >> 2, tg = lane & 3;
    int wrow = (wid & 3) * 16;
    int wcol = (wid >> 2) * 32;

    uint2 areg[4];
    auto ldgA = [&](int j) {
        int n = ng0 + j;
#pragma unroll
        for (int i = 0; i < 4; i++) {
            int idx = tid + i * 256;            // 1024 float4 units
            int r = idx >> 4, c = idx & 15;
            float4 v = *(const float4*)(x + (size_t)(bg0 + r) * 8192 + n * 64 + c * 4);
            areg[i] = make_uint2(pack2(v.x, v.y), pack2(v.z, v.w));
        }
    };
    auto stsA = [&](int s) {
        char* Ab = sm1 + s * S1BUF;
#pragma unroll
        for (int i = 0; i < 4; i++) {
            int idx = tid + i * 256;
            int r = idx >> 4, c = idx & 15;
            *(uint2*)(Ab + r * S1PITCH + c * 8) = areg[i];
        }
    };
    auto cpB = [&](int j, int s) {
        int n = ng0 + j;
        char* Bb = sm1 + s * S1BUF + S1TILE;
#pragma unroll
        for (int i = 0; i < 2; i++) {
            int idx = tid + i * 256;            // 512 16B units: 64 rows x 8
            int r = idx >> 3, c = idx & 7;
            cp16(Bb + r * S1PITCH + c * 16, g_w1h + ((size_t)n * 64 + r) * 64 + c * 8);
        }
        cp_commit();
    };

    float acc[4][4][4];
#pragma unroll
    for (int a = 0; a < 4; a++)
#pragma unroll
        for (int b = 0; b < 4; b++)
#pragma unroll
            for (int c = 0; c < 4; c++) acc[a][b][c] = 0.0f;

    ldgA(0); stsA(0); cpB(0, 0);

    int arow = wrow + (lane & 15);
    int acolh = (lane >> 4) * 8;
    int brow_base = ((lane >> 4) << 3) + (lane & 7);
    int bcolh = ((lane >> 3) & 1) * 8;

#pragma unroll
    for (int j = 0; j < 4; j++) {
        int s = j & 1, o = s ^ 1;
        if (j < 3) ldgA(j + 1);
        cp_wait<0>();
        __syncthreads();
        if (j < 3) cpB(j + 1, o);
        char* Ab = sm1 + s * S1BUF;
        char* Bb = Ab + S1TILE;
#pragma unroll
        for (int kk = 0; kk < 4; kk++) {
            int k0 = kk * 16;
            unsigned a0, a1, a2, a3;
            ldsm4(a0, a1, a2, a3, Ab + arow * S1PITCH + (k0 + acolh) * 2);
#pragma unroll
            for (int p = 0; p < 2; p++) {
                unsigned b0g0, b1g0, b0g1, b1g1;
                ldsm4(b0g0, b1g0, b0g1, b1g1,
                      Bb + (wcol + p * 16 + brow_base) * S1PITCH + (k0 + bcolh) * 2);
                mma_f16(acc[j][2*p][0], acc[j][2*p][1], acc[j][2*p][2], acc[j][2*p][3],
                        a0, a1, a2, a3, b0g0, b1g0);
                mma_f16(acc[j][2*p+1][0], acc[j][2*p+1][1], acc[j][2*p+1][2], acc[j][2*p+1][3],
                        a0, a1, a2, a3, b0g1, b1g1);
            }
        }
        if (j < 3) stsA(o);
    }

    // flush: t[b_local][m][ng0..ng0+3] packed fp16 (8B over 4 n)
#pragma unroll
    for (int nt = 0; nt < 4; nt++) {
#pragma unroll
        for (int rr = 0; rr < 2; rr++) {
#pragma unroll
            for (int c = 0; c < 2; c++) {
                int row = b0l + wrow + g + rr * 8;
                int col = wcol + nt * 8 + tg * 2 + c;
                int s = rr * 2 + c;
                uint2 v = make_uint2(pack2(acc[0][nt][s], acc[1][nt][s]),
                                     pack2(acc[2][nt][s], acc[3][nt][s]));
                *(uint2*)(th + ((size_t)row * 64 + col) * 128 + ng0) = v;
            }
        }
    }
}

// ---------------- stage-2 body: 128b x 128o (o-full), 3-stage cp.async ----------------
#define S2PITCH 80                      // bytes per row (40 halves)
#define S2ATILE (128 * S2PITCH)         // 10240 B
#define S2BTILE (128 * S2PITCH)         // 10240 B (128 o rows)
#define S2BUF   (S2ATILE + S2BTILE)     // 20480 B
__device__ __forceinline__ void s2_body(char* sm2, float* __restrict__ out,
                                        int id, int chunk) {
    int b0l = (id & 15) * 128;
    int bg0 = chunk * BCH + b0l;
    int m  = id >> 4;
    const __half* th = g_th + (size_t)(chunk & 1) * CHSZ;
    int tid = threadIdx.x;
    int wid = tid >> 5, lane = tid & 31, g = lane >> 2, tg = lane & 3;
    int wrow = (wid & 3) * 32;
    int wcol = (wid >> 2) * 64;

    auto issue = [&](int kc, int s) {
        int k0 = kc * 32;
        char* Ab = sm2 + s * S2BUF;
        char* Bb = Ab + S2ATILE;
#pragma unroll
        for (int i = 0; i < 2; i++) {            // A: 512 units, 128 rows x 4
            int idx = tid + i * 256;
            int r = idx >> 2, c = idx & 3;
            cp16(Ab + r * S2PITCH + c * 16,
                 th + ((size_t)(b0l + r) * 64 + m) * 128 + k0 + c * 8);
        }
#pragma unroll
        for (int i = 0; i < 2; i++) {            // B: 512 units, 128 o-rows x 4
            int idx = tid + i * 256;
            int r = idx >> 2, c = idx & 3;
            cp16(Bb + r * S2PITCH + c * 16,
                 g_w2h + ((size_t)m * 128 + r) * 128 + k0 + c * 8);
        }
        cp_commit();
    };

    float acc[2][8][4];
#pragma unroll
    for (int a = 0; a < 2; a++)
#pragma unroll
        for (int b = 0; b < 8; b++)
#pragma unroll
            for (int c = 0; c < 4; c++) acc[a][b][c] = 0.0f;

    issue(0, 0);
    issue(1, 1);

    int arow_off = lane & 15;
    int acolh = (lane >> 4) * 8;
    int brow_base = ((lane >> 4) << 3) + (lane & 7);
    int bcolh = ((lane >> 3) & 1) * 8;

#pragma unroll
    for (int kc = 0; kc < 4; kc++) {
        int s = kc % 3;
        if (kc < 3) cp_wait<1>(); else cp_wait<0>();
        __syncthreads();
        if (kc < 2) issue(kc + 2, (kc + 2) % 3);
        char* Ab = sm2 + s * S2BUF;
        char* Bb = Ab + S2ATILE;
#pragma unroll
        for (int kk = 0; kk < 2; kk++) {
            int k0 = kk * 16;
            unsigned am[2][4];
#pragma unroll
            for (int mr = 0; mr < 2; mr++)
                ldsm4(am[mr][0], am[mr][1], am[mr][2], am[mr][3],
                      Ab + (wrow + mr * 16 + arow_off) * S2PITCH + (k0 + acolh) * 2);
#pragma unroll
            for (int p = 0; p < 4; p++) {
                unsigned b0g0, b1g0, b0g1, b1g1;
                ldsm4(b0g0, b1g0, b0g1, b1g1,
                      Bb + (wcol + p * 16 + brow_base) * S2PITCH + (k0 + bcolh) * 2);
#pragma unroll
                for (int mr = 0; mr < 2; mr++) {
                    mma_f16(acc[mr][2*p][0], acc[mr][2*p][1], acc[mr][2*p][2], acc[mr][2*p][3],
                            am[mr][0], am[mr][1], am[mr][2], am[mr][3], b0g0, b1g0);
                    mma_f16(acc[mr][2*p+1][0], acc[mr][2*p+1][1], acc[mr][2*p+1][2], acc[mr][2*p+1][3],
                            am[mr][0], am[mr][1], am[mr][2], am[mr][3], b0g1, b1g1);
                }
            }
        }
    }

    // flush: out[b][m*128 + o]
#pragma unroll
    for (int mr = 0; mr < 2; mr++) {
#pragma unroll
        for (int nt = 0; nt < 8; nt++) {
            int col = wcol + nt * 8 + tg * 2;
            int r = bg0 + wrow + mr * 16 + g;
            float* dst = out + (size_t)r * 8192 + m * 128 + col;
            *(float2*)dst = make_float2(acc[mr][nt][0], acc[mr][nt][1]);
            *(float2*)(dst + (size_t)8 * 8192) = make_float2(acc[mr][nt][2], acc[mr][nt][3]);
        }
    }
}

// ---------------- fused GEMM kernel: role by blockIdx ----------------
// mode 0: all blocks s1(chunk_a).  grid 1024
// mode 1: even blocks s1(chunk_a), odd blocks s2(chunk_b).  grid 2048
// mode 2: all blocks s2(chunk_b).  grid 1024
__global__ __launch_bounds__(256, 2) void gemm_fused(const float* __restrict__ x,
                                                     float* __restrict__ out,
                                                     int chunk_a, int chunk_b, int mode) {
    extern __shared__ char smem[];
    int bid = blockIdx.x;
    bool do_s1;
    int id;
    if (mode == 0)      { do_s1 = true;  id = bid; }
    else if (mode == 2) { do_s1 = false; id = bid; }
    else                { do_s1 = (bid & 1) == 0; id = bid >> 1; }
    if (do_s1) s1_body(smem, x, id, chunk_a);
    else       s2_body(smem, out, id, chunk_b);
}

// ---------------- launch ----------------
extern "C" void kernel_launch(void* const* d_in, const int* in_sizes, int n_in,
                              void* d_out, int out_size) {
    const float* x = nullptr;
    const float* c1 = nullptr;
    const float* c2 = nullptr;
    for (int i = 0; i < n_in; i++) {
        if (in_sizes[i] == BROWS * 8192)            x  = (const float*)d_in[i];
        else if (in_sizes[i] == NB1 * I1 * MMID)    c1 = (const float*)d_in[i];
        else if (in_sizes[i] == MMID * NB1 * O2)    c2 = (const float*)d_in[i];
    }

    const int smem_sm = (NB1 * O2 + O2 * 132) * sizeof(float);    // ~130 KB
    const int smem_g  = 3 * S2BUF;                                // 61440 B (covers s1's 36.9 KB too)
    cudaFuncSetAttribute(softmax_fused_kernel, cudaFuncAttributeMaxDynamicSharedMemorySize, smem_sm);
    cudaFuncSetAttribute(gemm_fused, cudaFuncAttributeMaxDynamicSharedMemorySize, smem_g);

    float* out = (float*)d_out;
    softmax_fused_kernel<<<NB1 + MMID, 128, smem_sm>>>(c1, c2);
    gemm_fused<<<1024, 256, smem_g>>>(x, out, 0, 0, 0);   // s1(c0)
    gemm_fused<<<2048, 256, smem_g>>>(x, out, 1, 0, 1);   // s1(c1) || s2(c0)
    gemm_fused<<<1024, 256, smem_g>>>(x, out, 1, 1, 2);   // s2(c1)
}